// round 15
// baseline (speedup 1.0000x reference)
#include <cuda_runtime.h>
#include <cuda_fp16.h>
#include <math.h>
#include <stdint.h>

// Problem constants
#define BB   64
#define NN   1024
#define DD   256
#define HH   256
#define G3   768            // 3*H
#define NB   (BB*NN)        // 65536 rows
#define TG   32             // rows per unit in seq kernel
#define PITCH 264           // fp16 pitch for A smem tiles (132 u32; LDSM conflict-free)

// ---------------- scratch (device globals) ------------------------------------
__device__ __align__(16) __half g_h[NB*HH];     // hidden states fp16 (32 MB)
__device__ __align__(16) __half g_x_h[NB*DD];   // fp16 activations
// hi-only frag-packed weights: [n][ks][tq] -> uint2 {hi0, hi1}
__device__ __align__(16) uint2 g_wih_h2[G3*64];
__device__ __align__(16) uint2 g_whh_h2[G3*64];
__device__ unsigned short g_depth[NB];
__device__ int   g_cnt    [BB*NN];
__device__ int   g_rbstart[BB*NN];
__device__ int   g_rptr   [NN+1];
__device__ int   g_sched  [NB];
__device__ int   g_bmax   [BB];
__device__ int   g_maxd;
__device__ int   g_flag   [NB];      // per-node completion counter (4 quarters)
__device__ int   g_uptr   [NN+2];    // per-level unit prefix
__device__ int   g_unit_total;
__device__ unsigned g_unit_ctr;
__device__ unsigned g_bar_count = 0;
__device__ unsigned g_bar_gen   = 0;
__device__ unsigned g_leaf_count[8];

// ---------------- helpers ------------------------------------------------------
__device__ __forceinline__ void mma16816(float* c,
        uint32_t a0, uint32_t a1, uint32_t a2, uint32_t a3,
        uint32_t b0, uint32_t b1) {
    asm("mma.sync.aligned.m16n8k16.row.col.f32.f16.f16.f32 "
        "{%0,%1,%2,%3}, {%4,%5,%6,%7}, {%8,%9}, {%0,%1,%2,%3};"
        : "+f"(c[0]), "+f"(c[1]), "+f"(c[2]), "+f"(c[3])
        : "r"(a0), "r"(a1), "r"(a2), "r"(a3), "r"(b0), "r"(b1));
}
__device__ __forceinline__ void ldsm4(uint32_t addr, uint32_t* r) {
    asm volatile("ldmatrix.sync.aligned.m8n8.x4.shared.b16 {%0,%1,%2,%3}, [%4];"
        : "=r"(r[0]), "=r"(r[1]), "=r"(r[2]), "=r"(r[3]) : "r"(addr));
}
__device__ __forceinline__ uint32_t smem_u32(const void* p) {
    uint32_t a;
    asm("{ .reg .u64 t; cvta.to.shared.u64 t, %1; cvt.u32.u64 %0, t; }" : "=r"(a) : "l"(p));
    return a;
}
__device__ __forceinline__ uint32_t pack_h2(float x, float y) {
    __half2 h = __floats2half2_rn(x, y);
    return *reinterpret_cast<uint32_t*>(&h);
}
__device__ __forceinline__ float2 unpack_h2(uint32_t v) {
    __half2 h = *reinterpret_cast<__half2*>(&v);
    return __half22float2(h);
}
__device__ __forceinline__ float sigm(float x) { return 1.0f / (1.0f + expf(-x)); }

// Hierarchical grid barrier (used only by prep_sched, 64 CTAs).
__device__ __forceinline__ void grid_barrier() {
    __threadfence();
    __syncthreads();
    if (threadIdx.x == 0) {
        unsigned gen = *(volatile unsigned*)&g_bar_gen;
        int leaf = blockIdx.x & 7;
        unsigned gsz = (gridDim.x >> 3) + ((blockIdx.x & 7) < (gridDim.x & 7) ? 1u : 0u);
        if (atomicAdd(&g_leaf_count[leaf], 1u) == gsz - 1u) {
            g_leaf_count[leaf] = 0u;
            __threadfence();
            if (atomicAdd(&g_bar_count, 1u) == 7u) {
                g_bar_count = 0u;
                __threadfence();
                *(volatile unsigned*)&g_bar_gen = gen + 1u;
            }
        }
        while (*(volatile unsigned*)&g_bar_gen == gen) { __nanosleep(64); }
        __threadfence();
    }
    __syncthreads();
}

// ---------------- fused prep + scheduler (64 CTAs x 256, persistent) -----------
__global__ void __launch_bounds__(256) prep_sched_kernel(
        const float* __restrict__ wih, const float* __restrict__ whh,
        const int* __restrict__ lpi) {
    __shared__ int            jb[NN];
    __shared__ unsigned short db[NN];
    __shared__ int            scnt[NN];
    __shared__ int            stot[NN];
    __shared__ int            srptr[NN+1];
    __shared__ int            smax;
    int b = blockIdx.x, tid = threadIdx.x;

    // ---- phase 0a: weight frag-pack (distributed over all 64x256 threads)
    for (int e = b * 256 + tid; e < G3*64; e += 64*256) {
        int n  = e >> 6;
        int r  = e & 63;
        int ks = r >> 2, tq = r & 3;
        int k0 = 2*(ks*8 + tq);
        {
            uint2 v;
            v.x = pack_h2(wih[n*256 + k0],     wih[n*256 + k0 + 1]);
            v.y = pack_h2(wih[n*256 + k0 + 8], wih[n*256 + k0 + 9]);
            g_wih_h2[e] = v;
        }
        {
            uint2 v;
            v.x = pack_h2(whh[n*256 + k0],     whh[n*256 + k0 + 1]);
            v.y = pack_h2(whh[n*256 + k0 + 8], whh[n*256 + k0 + 9]);
            g_whh_h2[e] = v;
        }
    }
    // zero per-node flags for this batch + reset unit counter
    for (int i = tid; i < NN; i += 256) g_flag[b*NN + i] = 0;
    if (b == 0 && tid == 0) g_unit_ctr = 0u;

    // ---- phase 0b: per-batch depths via pointer doubling
    if (tid == 0) smax = 0;
    for (int i = tid; i < NN; i += 256) {
        jb[i] = (i == 0) ? 0 : lpi[b*NN + i];
        db[i] = (i == 0) ? 0 : 1;
        scnt[i] = 0;
    }
    __syncthreads();
    #pragma unroll 1
    for (int s = 0; s < 10; s++) {
        int nd[4], nj[4];
        #pragma unroll
        for (int u = 0; u < 4; u++) {
            int i = tid + u * 256;
            int j = jb[i];
            nd[u] = db[i] + db[j];
            nj[u] = jb[j];
        }
        __syncthreads();
        #pragma unroll
        for (int u = 0; u < 4; u++) {
            int i = tid + u * 256;
            db[i] = (unsigned short)nd[u];
            jb[i] = nj[u];
        }
        __syncthreads();
    }
    int lm = 0;
    for (int i = tid; i < NN; i += 256) {
        atomicAdd(&scnt[db[i]], 1);
        lm = max(lm, (int)db[i]);
    }
    atomicMax(&smax, lm);
    __syncthreads();
    if (tid == 0) g_bmax[b] = smax;
    for (int i = tid; i < NN; i += 256) {
        g_depth[b*NN + i] = db[i];
        g_cnt  [b*NN + i] = scnt[i];
    }
    grid_barrier();

    // ---- phase 1: global level prefix + unit prefix (CTA 0)
    if (b == 0) {
        for (int r = tid; r < NN; r += 256) {
            int s = 0;
            for (int bb = 0; bb < BB; bb++) {
                g_rbstart[bb*NN + r] = s;
                s += g_cnt[bb*NN + r];
            }
            stot[r] = s;
        }
        __syncthreads();
        if (tid == 0) {
            int acc = 0;
            for (int i = 0; i < NN; i++) { srptr[i] = acc; acc += stot[i]; }
            srptr[NN] = acc;
            int md = 0;
            for (int bb = 0; bb < BB; bb++) md = max(md, g_bmax[bb]);
            g_maxd = md;
            int uacc = 0;
            for (int r = 0; r <= md; r++) {
                g_uptr[r] = uacc;
                int cnt = srptr[r+1] - srptr[r];
                uacc += ((cnt + TG - 1) / TG) * 4;
            }
            g_uptr[md + 1] = uacc;
            g_unit_total = uacc;
        }
        __syncthreads();
        for (int r = tid; r < NN; r += 256) {
            g_rptr[r] = srptr[r];
            for (int bb = 0; bb < BB; bb++) g_rbstart[bb*NN + r] += srptr[r];
        }
        if (tid == 0) g_rptr[NN] = srptr[NN];
    }
    grid_barrier();

    // ---- phase 2: scatter into depth-sorted schedule (per-batch CTA)
    for (int i = tid; i < NN; i += 256) scnt[i] = g_rbstart[b*NN + i];
    __syncthreads();
    for (int i = tid; i < NN; i += 256) {
        int d = g_depth[b*NN + i];
        int pos = atomicAdd(&scnt[d], 1);
        g_sched[pos] = (b << 10) | i;
    }
}

// ---------------- embeddings + first half of output (float4, 4 nodes/block) ----
__global__ void __launch_bounds__(256) embed_kernel(
                             const int* __restrict__ node_types,
                             const int* __restrict__ node_vals,
                             const int* __restrict__ child_positions,
                             const float* __restrict__ type_emb,
                             const float* __restrict__ pos_table,
                             const float* __restrict__ token_emb,
                             float* __restrict__ out) {
    int tid = threadIdx.x;
    int id  = blockIdx.x * 4 + (tid >> 6);
    int j   = tid & 63;
    int b = id >> 10, n = id & 1023;
    int tt = node_types[id];
    int cp = child_positions[id];
    int v0 = node_vals[2*id];
    int v1 = node_vals[2*id + 1];
    float4 te = ((const float4*)type_emb)[tt*64 + j];
    float4 pe = ((const float4*)pos_table)[cp*64 + j];
    float4 t0 = ((const float4*)token_emb)[v0*64 + j];
    float4 t1 = ((const float4*)token_emb)[v1*64 + j];
    float4 x, o;
    x.x = te.x*4.0f + pe.x*0.25f;  x.y = te.y*4.0f + pe.y*0.25f;
    x.z = te.z*4.0f + pe.z*0.25f;  x.w = te.w*4.0f + pe.w*0.25f;
    o.x = x.x + (t0.x + t1.x)*2.0f;  o.y = x.y + (t0.y + t1.y)*2.0f;
    o.z = x.z + (t0.z + t1.z)*2.0f;  o.w = x.w + (t0.w + t1.w)*2.0f;
    ((float4*)(out + (long)(n*BB + b) * (DD+HH)))[j] = o;
    uint2 hx;
    hx.x = pack_h2(x.x, x.y);
    hx.y = pack_h2(x.z, x.w);
    ((uint2*)(g_x_h + (long)id * DD))[j] = hx;
}

// ---------------- dataflow GRU kernel with FUSED input-gate GEMM ---------------
// Unit = (row-group of TG=32, quarter of 64 output cols). Per unit:
//  1. gather x rows (no deps) -> sX; run x-GEMM into Cx (fills wait time)
//  2. poll parents; gather h -> sH; run h-GEMM into Ch
//  3. fused GRU epilogue from Cx/Ch (gates never touch DRAM)
__global__ void __launch_bounds__(256, 2) seq_kernel(const int* __restrict__ lpi,
                                                     const float* __restrict__ bih,
                                                     const float* __restrict__ bhh,
                                                     float* __restrict__ out) {
    __shared__ __half sX[TG * PITCH];
    __shared__ __half sH[TG * PITCH];
    __shared__ int sMeta[TG];
    __shared__ int sPar[TG];
    __shared__ int sUptr[NN + 2];
    __shared__ int sU;
    int tid = threadIdx.x;
    int wid = tid >> 5, lane = tid & 31;
    int gid = lane >> 2, tq = lane & 3;
    int maxd = g_maxd;
    int total = g_unit_total;

    for (int i = tid; i <= maxd + 1; i += 256) sUptr[i] = g_uptr[i];

    int l7 = lane & 7, q = lane >> 3;
    uint32_t aoff = (((q & 1) * 8 + l7) * (PITCH/2) + (q >> 1) * 4) * 4;
    uint32_t adX[2], adH[2];
    #pragma unroll
    for (int mt = 0; mt < 2; mt++) {
        adX[mt] = smem_u32(sX) + (mt * 16) * (PITCH*2) + aoff;
        adH[mt] = smem_u32(sH) + (mt * 16) * (PITCH*2) + aoff;
    }
    __syncthreads();

    while (true) {
        if (tid == 0) sU = (int)atomicAdd(&g_unit_ctr, 1u);
        __syncthreads();
        int u = sU;
        if (u >= total) break;
        // binary search: largest r with sUptr[r] <= u
        int lo = 0, hi = maxd;
        while (lo < hi) {
            int mid = (lo + hi + 1) >> 1;
            if (sUptr[mid] <= u) lo = mid; else hi = mid - 1;
        }
        int r = lo;
        int start = g_rptr[r];
        int cnt   = g_rptr[r+1] - start;
        int local = u - sUptr[r];
        int gidx = local >> 2, quarter = local & 3;
        int t0 = start + gidx * TG;
        int tc = cnt - gidx * TG; if (tc > TG) tc = TG;
        if (tid < TG) {
            if (tid < tc) {
                int s = g_sched[t0 + tid];
                sMeta[tid] = s;
                int b = s >> 10, i = s & 1023;
                sPar[tid] = (i == 0) ? -1 : ((b << 10) | lpi[b*NN + i]);
            } else { sMeta[tid] = 0; sPar[tid] = -1; }
        }
        __syncthreads();

        int nbase = quarter * 64 + 8 * wid;
        int cp = nbase + tq * 2;               // this thread's output col

        // ---- gather x rows (no dependency) -> sX
        for (int idx = tid; idx < TG * 32; idx += 256) {
            int t = idx >> 5, k16 = idx & 31;
            long row = (long)sMeta[t];
            uint4 v = ((const uint4*)(g_x_h + row * DD))[k16];
            *(uint4*)((char*)sX + t * (PITCH*2) + k16 * 16) = v;
        }
        __syncthreads();

        // ---- x-GEMM into Cx (runs while parents may still be in flight)
        float Cx[2][3][4];
        #pragma unroll
        for (int mt = 0; mt < 2; mt++)
            #pragma unroll
            for (int jj = 0; jj < 3; jj++)
                #pragma unroll
                for (int qq = 0; qq < 4; qq++) Cx[mt][jj][qq] = 0.0f;
        {
            uint2 bwA[3], bwB[3];
            #pragma unroll
            for (int jj = 0; jj < 3; jj++)
                bwA[jj] = g_wih_h2[(jj*256 + nbase + gid) * 64 + tq];
            #pragma unroll 1
            for (int ks = 0; ks < 16; ks++) {
                uint2* cur = (ks & 1) ? bwB : bwA;
                uint2* nxt = (ks & 1) ? bwA : bwB;
                if (ks < 15) {
                    #pragma unroll
                    for (int jj = 0; jj < 3; jj++)
                        nxt[jj] = g_wih_h2[(jj*256 + nbase + gid) * 64 + (ks+1)*4 + tq];
                }
                uint32_t aF[2][4];
                #pragma unroll
                for (int mt = 0; mt < 2; mt++) ldsm4(adX[mt] + ks * 32, aF[mt]);
                #pragma unroll
                for (int jj = 0; jj < 3; jj++)
                    #pragma unroll
                    for (int mt = 0; mt < 2; mt++)
                        mma16816(Cx[mt][jj], aF[mt][0], aF[mt][1], aF[mt][2], aF[mt][3],
                                 cur[jj].x, cur[jj].y);
            }
        }

        // ---- wait for parents (flag reaches 4 when fully written)
        if (tid < TG) {
            int pr = sPar[tid];
            if (pr >= 0) {
                const volatile int* fp = (const volatile int*)&g_flag[pr];
                while (*fp < 4) { __nanosleep(32); }
                __threadfence();
            }
        }
        __syncthreads();

        // ---- gather parents (fp16 rows) -> sH
        for (int idx = tid; idx < TG * 32; idx += 256) {
            int t = idx >> 5, k16 = idx & 31;
            int pr = sPar[t];
            uint4 v;
            if (pr < 0) { v.x = v.y = v.z = v.w = 0u; }
            else        { v = ((const uint4*)(g_h + (long)pr * HH))[k16]; }
            *(uint4*)((char*)sH + t * (PITCH*2) + k16 * 16) = v;
        }
        __syncthreads();

        // ---- h-GEMM into Ch
        float Ch[2][3][4];
        #pragma unroll
        for (int mt = 0; mt < 2; mt++)
            #pragma unroll
            for (int jj = 0; jj < 3; jj++)
                #pragma unroll
                for (int qq = 0; qq < 4; qq++) Ch[mt][jj][qq] = 0.0f;
        {
            uint2 bwA[3], bwB[3];
            #pragma unroll
            for (int jj = 0; jj < 3; jj++)
                bwA[jj] = g_whh_h2[(jj*256 + nbase + gid) * 64 + tq];
            #pragma unroll 1
            for (int ks = 0; ks < 16; ks++) {
                uint2* cur = (ks & 1) ? bwB : bwA;
                uint2* nxt = (ks & 1) ? bwA : bwB;
                if (ks < 15) {
                    #pragma unroll
                    for (int jj = 0; jj < 3; jj++)
                        nxt[jj] = g_whh_h2[(jj*256 + nbase + gid) * 64 + (ks+1)*4 + tq];
                }
                uint32_t aF[2][4];
                #pragma unroll
                for (int mt = 0; mt < 2; mt++) ldsm4(adH[mt] + ks * 32, aF[mt]);
                #pragma unroll
                for (int jj = 0; jj < 3; jj++)
                    #pragma unroll
                    for (int mt = 0; mt < 2; mt++)
                        mma16816(Ch[mt][jj], aF[mt][0], aF[mt][1], aF[mt][2], aF[mt][3],
                                 cur[jj].x, cur[jj].y);
            }
        }

        // ---- fused GRU epilogue (gates in registers, never in DRAM)
        {
            float2 bir = *(const float2*)(bih + cp);
            float2 biz = *(const float2*)(bih + 256 + cp);
            float2 bin = *(const float2*)(bih + 512 + cp);
            float2 bhr = *(const float2*)(bhh + cp);
            float2 bhz = *(const float2*)(bhh + 256 + cp);
            float2 bhn = *(const float2*)(bhh + 512 + cp);
            #pragma unroll
            for (int mt = 0; mt < 2; mt++) {
                #pragma unroll
                for (int rh = 0; rh < 2; rh++) {
                    int lr = mt * 16 + gid + rh * 8;
                    if (lr >= tc) continue;
                    int s = sMeta[lr];
                    long row = (long)s;
                    int b = s >> 10, i = s & 1023;
                    uint32_t hpw = *(const uint32_t*)((char*)sH + lr * (PITCH*2) + cp * 2);
                    float2 hp = unpack_h2(hpw);
                    float rg0 = sigm(Cx[mt][0][rh*2]   + bir.x + Ch[mt][0][rh*2]   + bhr.x);
                    float rg1 = sigm(Cx[mt][0][rh*2+1] + bir.y + Ch[mt][0][rh*2+1] + bhr.y);
                    float zg0 = sigm(Cx[mt][1][rh*2]   + biz.x + Ch[mt][1][rh*2]   + bhz.x);
                    float zg1 = sigm(Cx[mt][1][rh*2+1] + biz.y + Ch[mt][1][rh*2+1] + bhz.y);
                    float ng0 = tanhf(Cx[mt][2][rh*2]   + bin.x + rg0 * (Ch[mt][2][rh*2]   + bhn.x));
                    float ng1 = tanhf(Cx[mt][2][rh*2+1] + bin.y + rg1 * (Ch[mt][2][rh*2+1] + bhn.y));
                    float h0 = (1.0f - zg0) * ng0 + zg0 * hp.x;
                    float h1 = (1.0f - zg1) * ng1 + zg1 * hp.y;
                    *(uint32_t*)(g_h + row * HH + cp) = pack_h2(h0, h1);
                    *(float2*)(out + ((long)(i*BB + b) * (DD+HH)) + DD + cp) = make_float2(h0, h1);
                }
            }
        }
        __threadfence();
        __syncthreads();
        if (tid < tc) atomicAdd(&g_flag[sMeta[tid]], 1);
    }
}

// ---------------- launch -------------------------------------------------------
extern "C" void kernel_launch(void* const* d_in, const int* in_sizes, int n_in,
                              void* d_out, int out_size) {
    const int*   node_types      = (const int*)  d_in[0];
    const int*   node_vals       = (const int*)  d_in[1];
    const int*   last_parent     = (const int*)  d_in[3];
    const int*   child_positions = (const int*)  d_in[4];
    const float* type_emb        = (const float*)d_in[5];
    const float* pos_table       = (const float*)d_in[6];
    const float* token_emb       = (const float*)d_in[7];
    const float* w_ih            = (const float*)d_in[8];
    const float* w_hh            = (const float*)d_in[9];
    const float* b_ih            = (const float*)d_in[10];
    const float* b_hh            = (const float*)d_in[11];
    float* out = (float*)d_out;

    prep_sched_kernel<<<BB, 256>>>(w_ih, w_hh, last_parent);
    embed_kernel<<<NB/4, 256>>>(node_types, node_vals, child_positions,
                                type_emb, pos_table, token_emb, out);
    seq_kernel<<<296, 256>>>(last_parent, b_ih, b_hh, out);
}

// round 16
// speedup vs baseline: 1.1505x; 1.1505x over previous
#include <cuda_runtime.h>
#include <cuda_fp16.h>
#include <math.h>
#include <stdint.h>

// Problem constants
#define BB   64
#define NN   1024
#define DD   256
#define HH   256
#define G3   768            // 3*H
#define NB   (BB*NN)        // 65536 rows
#define TG   32             // rows per unit in seq kernel
#define PITCH 264           // fp16 pitch for A smem tiles (132 u32; LDSM conflict-free)

// ---------------- scratch (device globals) ------------------------------------
__device__ __align__(16) __half g_gi_h[NB*G3];  // input gates fp16 (96 MB)
__device__ __align__(16) __half g_h[NB*HH];     // hidden states fp16 (32 MB)
__device__ __align__(16) __half g_x_h[NB*DD];   // fp16 activations
// hi-only frag-packed weights: [n][ks][tq] -> uint2 {hi0, hi1}
__device__ __align__(16) uint2 g_wih_h2[G3*64];
__device__ __align__(16) uint2 g_whh_h2[G3*64];
__device__ int   g_rptr   [NN+1];
__device__ int   g_sched  [NB];
__device__ int   g_bmax   [BB];
__device__ int   g_maxd;
__device__ int   g_flag   [NB];      // per-node completion counter (4 quarters)
__device__ int   g_uptr   [NN+2];    // per-level unit prefix
__device__ int   g_stot   [NN];      // level totals (atomic-accumulated)
__device__ int   g_cursor [NN];      // per-level slot cursor
__device__ int   g_unit_total;
__device__ unsigned g_unit_ctr;
__device__ unsigned g_bar_count = 0;
__device__ unsigned g_bar_gen   = 0;
__device__ unsigned g_leaf_count[8];

// ---------------- helpers ------------------------------------------------------
__device__ __forceinline__ void mma16816(float* c,
        uint32_t a0, uint32_t a1, uint32_t a2, uint32_t a3,
        uint32_t b0, uint32_t b1) {
    asm("mma.sync.aligned.m16n8k16.row.col.f32.f16.f16.f32 "
        "{%0,%1,%2,%3}, {%4,%5,%6,%7}, {%8,%9}, {%0,%1,%2,%3};"
        : "+f"(c[0]), "+f"(c[1]), "+f"(c[2]), "+f"(c[3])
        : "r"(a0), "r"(a1), "r"(a2), "r"(a3), "r"(b0), "r"(b1));
}
__device__ __forceinline__ void ldsm4(uint32_t addr, uint32_t* r) {
    asm volatile("ldmatrix.sync.aligned.m8n8.x4.shared.b16 {%0,%1,%2,%3}, [%4];"
        : "=r"(r[0]), "=r"(r[1]), "=r"(r[2]), "=r"(r[3]) : "r"(addr));
}
__device__ __forceinline__ uint32_t smem_u32(const void* p) {
    uint32_t a;
    asm("{ .reg .u64 t; cvta.to.shared.u64 t, %1; cvt.u32.u64 %0, t; }" : "=r"(a) : "l"(p));
    return a;
}
__device__ __forceinline__ uint32_t pack_h2(float x, float y) {
    __half2 h = __floats2half2_rn(x, y);
    return *reinterpret_cast<uint32_t*>(&h);
}
__device__ __forceinline__ float2 unpack_h2(uint32_t v) {
    __half2 h = *reinterpret_cast<__half2*>(&v);
    return __half22float2(h);
}
__device__ __forceinline__ float sigm(float x) { return 1.0f / (1.0f + expf(-x)); }

// Hierarchical grid barrier (used only by prep_sched, 64 CTAs).
__device__ __forceinline__ void grid_barrier() {
    __threadfence();
    __syncthreads();
    if (threadIdx.x == 0) {
        unsigned gen = *(volatile unsigned*)&g_bar_gen;
        int leaf = blockIdx.x & 7;
        unsigned gsz = (gridDim.x >> 3) + ((blockIdx.x & 7) < (gridDim.x & 7) ? 1u : 0u);
        if (atomicAdd(&g_leaf_count[leaf], 1u) == gsz - 1u) {
            g_leaf_count[leaf] = 0u;
            __threadfence();
            if (atomicAdd(&g_bar_count, 1u) == 7u) {
                g_bar_count = 0u;
                __threadfence();
                *(volatile unsigned*)&g_bar_gen = gen + 1u;
            }
        }
        while (*(volatile unsigned*)&g_bar_gen == gen) { __nanosleep(64); }
        __threadfence();
    }
    __syncthreads();
}

// ---------------- fused prep + scheduler (64 CTAs x 256, parallel phase 1) -----
__global__ void __launch_bounds__(256) prep_sched_kernel(
        const float* __restrict__ wih, const float* __restrict__ whh,
        const int* __restrict__ lpi) {
    __shared__ int            jb[NN];
    __shared__ unsigned short db[NN];
    __shared__ int            scnt[NN];
    __shared__ int            scur[NN];
    __shared__ int            ssum[256];
    __shared__ int            smax;
    int b = blockIdx.x, tid = threadIdx.x;

    // ---- phase 0a: weight frag-pack (distributed over all 64x256 threads)
    for (int e = b * 256 + tid; e < G3*64; e += 64*256) {
        int n  = e >> 6;
        int r  = e & 63;
        int ks = r >> 2, tq = r & 3;
        int k0 = 2*(ks*8 + tq);
        {
            uint2 v;
            v.x = pack_h2(wih[n*256 + k0],     wih[n*256 + k0 + 1]);
            v.y = pack_h2(wih[n*256 + k0 + 8], wih[n*256 + k0 + 9]);
            g_wih_h2[e] = v;
        }
        {
            uint2 v;
            v.x = pack_h2(whh[n*256 + k0],     whh[n*256 + k0 + 1]);
            v.y = pack_h2(whh[n*256 + k0 + 8], whh[n*256 + k0 + 9]);
            g_whh_h2[e] = v;
        }
    }
    // zero flags + this CTA's slice of level totals; reset unit counter
    for (int i = tid; i < NN; i += 256) g_flag[b*NN + i] = 0;
    if (tid < 16) g_stot[b*16 + tid] = 0;
    if (b == 0 && tid == 0) g_unit_ctr = 0u;

    // ---- phase 0b: per-batch depths via pointer doubling
    if (tid == 0) smax = 0;
    for (int i = tid; i < NN; i += 256) {
        jb[i] = (i == 0) ? 0 : lpi[b*NN + i];
        db[i] = (i == 0) ? 0 : 1;
        scnt[i] = 0;
    }
    __syncthreads();
    #pragma unroll 1
    for (int s = 0; s < 10; s++) {
        int nd[4], nj[4];
        #pragma unroll
        for (int u = 0; u < 4; u++) {
            int i = tid + u * 256;
            int j = jb[i];
            nd[u] = db[i] + db[j];
            nj[u] = jb[j];
        }
        __syncthreads();
        #pragma unroll
        for (int u = 0; u < 4; u++) {
            int i = tid + u * 256;
            db[i] = (unsigned short)nd[u];
            jb[i] = nj[u];
        }
        __syncthreads();
    }
    int lm = 0;
    for (int i = tid; i < NN; i += 256) {
        atomicAdd(&scnt[db[i]], 1);
        lm = max(lm, (int)db[i]);
    }
    atomicMax(&smax, lm);
    __syncthreads();
    if (tid == 0) g_bmax[b] = smax;
    grid_barrier();

    // ---- phase 1a: accumulate level totals (parallel atomics)
    for (int i = tid; i < NN; i += 256)
        if (scnt[i]) atomicAdd(&g_stot[i], scnt[i]);
    grid_barrier();

    // ---- phase 1b: CTA0 two-stage scan over 1024 level totals
    if (b == 0) {
        int base = tid * 4;
        int v0 = g_stot[base], v1 = g_stot[base+1], v2 = g_stot[base+2], v3 = g_stot[base+3];
        ssum[tid] = v0 + v1 + v2 + v3;
        __syncthreads();
        if (tid == 0) {
            int acc = 0;
            for (int t = 0; t < 256; t++) { int x = ssum[t]; ssum[t] = acc; acc += x; }
        }
        __syncthreads();
        int acc = ssum[tid];
        int p0 = acc, p1 = acc + v0, p2 = p1 + v1, p3 = p2 + v2;
        g_rptr[base] = p0;   g_cursor[base] = p0;
        g_rptr[base+1] = p1; g_cursor[base+1] = p1;
        g_rptr[base+2] = p2; g_cursor[base+2] = p2;
        g_rptr[base+3] = p3; g_cursor[base+3] = p3;
        if (tid == 255) g_rptr[NN] = p3 + v3;
        __syncthreads();
        if (tid == 0) {
            int md = 0;
            for (int bb = 0; bb < BB; bb++) md = max(md, g_bmax[bb]);
            g_maxd = md;
            int uacc = 0;
            for (int r = 0; r <= md; r++) {
                g_uptr[r] = uacc;
                int cnt = g_rptr[r+1] - g_rptr[r];
                uacc += ((cnt + TG - 1) / TG) * 4;
            }
            g_uptr[md + 1] = uacc;
            g_unit_total = uacc;
        }
    }
    grid_barrier();

    // ---- phase 1c: per-(batch,level) base slots via cursor atomics
    for (int i = tid; i < NN; i += 256)
        scur[i] = scnt[i] ? atomicAdd(&g_cursor[i], scnt[i]) : 0;
    __syncthreads();

    // ---- phase 2: scatter into depth-sorted schedule
    for (int i = tid; i < NN; i += 256) {
        int d = db[i];
        int pos = atomicAdd(&scur[d], 1);
        g_sched[pos] = (b << 10) | i;
    }
}

// ---------------- embeddings + first half of output (float4, 4 nodes/block) ----
__global__ void __launch_bounds__(256) embed_kernel(
                             const int* __restrict__ node_types,
                             const int* __restrict__ node_vals,
                             const int* __restrict__ child_positions,
                             const float* __restrict__ type_emb,
                             const float* __restrict__ pos_table,
                             const float* __restrict__ token_emb,
                             float* __restrict__ out) {
    int tid = threadIdx.x;
    int id  = blockIdx.x * 4 + (tid >> 6);
    int j   = tid & 63;
    int b = id >> 10, n = id & 1023;
    int tt = node_types[id];
    int cp = child_positions[id];
    int v0 = node_vals[2*id];
    int v1 = node_vals[2*id + 1];
    float4 te = ((const float4*)type_emb)[tt*64 + j];
    float4 pe = ((const float4*)pos_table)[cp*64 + j];
    float4 t0 = ((const float4*)token_emb)[v0*64 + j];
    float4 t1 = ((const float4*)token_emb)[v1*64 + j];
    float4 x, o;
    x.x = te.x*4.0f + pe.x*0.25f;  x.y = te.y*4.0f + pe.y*0.25f;
    x.z = te.z*4.0f + pe.z*0.25f;  x.w = te.w*4.0f + pe.w*0.25f;
    o.x = x.x + (t0.x + t1.x)*2.0f;  o.y = x.y + (t0.y + t1.y)*2.0f;
    o.z = x.z + (t0.z + t1.z)*2.0f;  o.w = x.w + (t0.w + t1.w)*2.0f;
    ((float4*)(out + (long)(n*BB + b) * (DD+HH)))[j] = o;
    uint2 hx;
    hx.x = pack_h2(x.x, x.y);
    hx.y = pack_h2(x.z, x.w);
    ((uint2*)(g_x_h + (long)id * DD))[j] = hx;
}

// ---------------- GI GEMM: 512 threads, M=128/CTA, 3 N-chunks, single fp16 term
#define GI_SMEM (128 * PITCH * 2)   // fp16 A tile, bytes

__global__ void __launch_bounds__(512, 1) gi_mma_kernel(const float* __restrict__ bih) {
    extern __shared__ __half sA[];              // [128][PITCH]
    int tid = threadIdx.x;
    int wid = tid >> 5, lane = tid & 31;
    int gid = lane >> 2, tq = lane & 3;
    int wm = wid >> 3, wc = wid & 7;
    long row0 = (long)blockIdx.x * 128;

    {
        const uint32_t* src = (const uint32_t*)g_x_h + row0 * 128;
        uint32_t* dst = (uint32_t*)sA;
        for (int idx = tid; idx < 128 * 128; idx += 512) {
            int m = idx >> 7, j = idx & 127;
            dst[m * (PITCH/2) + j] = src[idx];
        }
    }
    __syncthreads();

    int l7 = lane & 7, q = lane >> 3;
    uint32_t aoff = (((q & 1) * 8 + l7) * (PITCH/2) + (q >> 1) * 4) * 4;
    uint32_t sAA = smem_u32(sA);
    uint32_t ad[4];
    #pragma unroll
    for (int mt = 0; mt < 4; mt++)
        ad[mt] = sAA + (wm * 64 + mt * 16) * (PITCH*2) + aoff;

    for (int c = 0; c < 3; c++) {
        float C[4][4][4];
        #pragma unroll
        for (int mt = 0; mt < 4; mt++)
            #pragma unroll
            for (int nt = 0; nt < 4; nt++)
                #pragma unroll
                for (int qq = 0; qq < 4; qq++) C[mt][nt][qq] = 0.0f;

        #pragma unroll 2
        for (int ks = 0; ks < 16; ks++) {
            uint32_t aF[4][4];
            #pragma unroll
            for (int mt = 0; mt < 4; mt++) ldsm4(ad[mt] + ks * 32, aF[mt]);
            uint2 bw[4];
            #pragma unroll
            for (int nt = 0; nt < 4; nt++) {
                int n = c * 256 + wc * 32 + nt * 8 + gid;
                bw[nt] = g_wih_h2[n * 64 + ks * 4 + tq];
            }
            #pragma unroll
            for (int nt = 0; nt < 4; nt++)
                #pragma unroll
                for (int mt = 0; mt < 4; mt++)
                    mma16816(C[mt][nt], aF[mt][0], aF[mt][1], aF[mt][2], aF[mt][3],
                             bw[nt].x, bw[nt].y);
        }
        #pragma unroll
        for (int mt = 0; mt < 4; mt++) {
            long r = row0 + wm * 64 + mt * 16 + gid;
            #pragma unroll
            for (int nt = 0; nt < 4; nt++) {
                int col = c * 256 + wc * 32 + nt * 8 + tq * 2;
                float2 bv = *(const float2*)(bih + col);
                *(uint32_t*)(g_gi_h + r * G3 + col) =
                    pack_h2(C[mt][nt][0] + bv.x, C[mt][nt][1] + bv.y);
                *(uint32_t*)(g_gi_h + (r + 8) * G3 + col) =
                    pack_h2(C[mt][nt][2] + bv.x, C[mt][nt][3] + bv.y);
            }
        }
    }
}

// ---------------- dataflow GRU kernel (persistent, 256 thr, 2 CTAs/SM) ---------
// Units in level order; unit = (row-group of TG=32, quarter of 64 output cols).
// CTAs claim units via global atomic (claim order respects dependencies).
// A unit polls each parent's flag (==4 after all 4 quarters wrote) before use.
__global__ void __launch_bounds__(256, 2) seq_kernel(const int* __restrict__ lpi,
                                                     const float* __restrict__ bhh,
                                                     float* __restrict__ out) {
    __shared__ __half sH[TG * PITCH];
    __shared__ int sMeta[TG];
    __shared__ int sPar[TG];
    __shared__ int sUptr[NN + 2];
    __shared__ int sU;
    int tid = threadIdx.x;
    int wid = tid >> 5, lane = tid & 31;
    int gid = lane >> 2, tq = lane & 3;
    int maxd = g_maxd;
    int total = g_unit_total;

    for (int i = tid; i <= maxd + 1; i += 256) sUptr[i] = g_uptr[i];

    int l7 = lane & 7, q = lane >> 3;
    uint32_t aoff = (((q & 1) * 8 + l7) * (PITCH/2) + (q >> 1) * 4) * 4;
    uint32_t sHA = smem_u32(sH);
    uint32_t ad[2];
    #pragma unroll
    for (int mt = 0; mt < 2; mt++)
        ad[mt] = sHA + (mt * 16) * (PITCH*2) + aoff;
    __syncthreads();

    while (true) {
        if (tid == 0) sU = (int)atomicAdd(&g_unit_ctr, 1u);
        __syncthreads();
        int u = sU;
        if (u >= total) break;
        // binary search: largest r with sUptr[r] <= u
        int lo = 0, hi = maxd;
        while (lo < hi) {
            int mid = (lo + hi + 1) >> 1;
            if (sUptr[mid] <= u) lo = mid; else hi = mid - 1;
        }
        int r = lo;
        int start = g_rptr[r];
        int cnt   = g_rptr[r+1] - start;
        int local = u - sUptr[r];
        int gidx = local >> 2, quarter = local & 3;
        int t0 = start + gidx * TG;
        int tc = cnt - gidx * TG; if (tc > TG) tc = TG;
        if (tid < TG) {
            if (tid < tc) {
                int s = g_sched[t0 + tid];
                sMeta[tid] = s;
                int b = s >> 10, i = s & 1023;
                sPar[tid] = (i == 0) ? -1 : ((b << 10) | lpi[b*NN + i]);
            } else { sMeta[tid] = 0; sPar[tid] = -1; }
        }
        __syncthreads();

        int nbase = quarter * 64 + 8 * wid;
        int cp = nbase + tq * 2;               // this thread's output col

        // -------- prefetch g_gi gate words for this thread's 4 rows
        uint32_t preR[4], preZ[4], preN[4];
        #pragma unroll
        for (int mt = 0; mt < 2; mt++)
            #pragma unroll
            for (int rh = 0; rh < 2; rh++) {
                int lr = mt * 16 + gid + rh * 8;
                long row = (long)sMeta[lr];
                const __half* gp = g_gi_h + row * G3;
                preR[mt*2+rh] = *(const uint32_t*)(gp + cp);
                preZ[mt*2+rh] = *(const uint32_t*)(gp + 256 + cp);
                preN[mt*2+rh] = *(const uint32_t*)(gp + 512 + cp);
            }

        // -------- wait for parents (flag reaches 4 when fully written)
        if (tid < TG) {
            int pr = sPar[tid];
            if (pr >= 0) {
                const volatile int* fp = (const volatile int*)&g_flag[pr];
                while (*fp < 4) { __nanosleep(32); }
                __threadfence();
            }
        }
        __syncthreads();

        // gather parents (fp16 rows, straight uint4 copy) -> smem
        for (int idx = tid; idx < TG * 32; idx += 256) {
            int t = idx >> 5, k16 = idx & 31;
            int pr = sPar[t];
            uint4 v;
            if (pr < 0) { v.x = v.y = v.z = v.w = 0u; }
            else        { v = ((const uint4*)(g_h + (long)pr * HH))[k16]; }
            *(uint4*)((char*)sH + t * (PITCH*2) + k16 * 16) = v;
        }
        __syncthreads();

        float C[2][3][4];
        #pragma unroll
        for (int mt = 0; mt < 2; mt++)
            #pragma unroll
            for (int jj = 0; jj < 3; jj++)
                #pragma unroll
                for (int qq = 0; qq < 4; qq++) C[mt][jj][qq] = 0.0f;

        // double-buffered B frags across ks
        uint2 bwA[3], bwB[3];
        #pragma unroll
        for (int jj = 0; jj < 3; jj++)
            bwA[jj] = g_whh_h2[(jj*256 + nbase + gid) * 64 + tq];
        #pragma unroll 1
        for (int ks = 0; ks < 16; ks++) {
            uint2* cur = (ks & 1) ? bwB : bwA;
            uint2* nxt = (ks & 1) ? bwA : bwB;
            if (ks < 15) {
                #pragma unroll
                for (int jj = 0; jj < 3; jj++)
                    nxt[jj] = g_whh_h2[(jj*256 + nbase + gid) * 64 + (ks+1)*4 + tq];
            }
            uint32_t aF[2][4];
            #pragma unroll
            for (int mt = 0; mt < 2; mt++) ldsm4(ad[mt] + ks * 32, aF[mt]);
            #pragma unroll
            for (int jj = 0; jj < 3; jj++)
                #pragma unroll
                for (int mt = 0; mt < 2; mt++)
                    mma16816(C[mt][jj], aF[mt][0], aF[mt][1], aF[mt][2], aF[mt][3],
                             cur[jj].x, cur[jj].y);
        }

        // fused GRU epilogue using prefetched gates
        {
            float2 br = *(const float2*)(bhh + cp);
            float2 bz = *(const float2*)(bhh + 256 + cp);
            float2 bn = *(const float2*)(bhh + 512 + cp);
            #pragma unroll
            for (int mt = 0; mt < 2; mt++) {
                #pragma unroll
                for (int rh = 0; rh < 2; rh++) {
                    int lr = mt * 16 + gid + rh * 8;
                    if (lr >= tc) continue;
                    int s = sMeta[lr];
                    long row = (long)s;
                    int b = s >> 10, i = s & 1023;
                    float2 gr = unpack_h2(preR[mt*2+rh]);
                    float2 gz = unpack_h2(preZ[mt*2+rh]);
                    float2 gn = unpack_h2(preN[mt*2+rh]);
                    uint32_t hpw = *(const uint32_t*)((char*)sH + lr * (PITCH*2) + cp * 2);
                    float2 hp = unpack_h2(hpw);
                    float rg0 = sigm(gr.x + C[mt][0][rh*2]   + br.x);
                    float rg1 = sigm(gr.y + C[mt][0][rh*2+1] + br.y);
                    float zg0 = sigm(gz.x + C[mt][1][rh*2]   + bz.x);
                    float zg1 = sigm(gz.y + C[mt][1][rh*2+1] + bz.y);
                    float ng0 = tanhf(gn.x + (C[mt][2][rh*2]   + bn.x) * rg0);
                    float ng1 = tanhf(gn.y + (C[mt][2][rh*2+1] + bn.y) * rg1);
                    float h0 = (1.0f - zg0) * ng0 + zg0 * hp.x;
                    float h1 = (1.0f - zg1) * ng1 + zg1 * hp.y;
                    *(uint32_t*)(g_h + row * HH + cp) = pack_h2(h0, h1);
                    *(float2*)(out + ((long)(i*BB + b) * (DD+HH)) + DD + cp) = make_float2(h0, h1);
                }
            }
        }
        __threadfence();
        __syncthreads();
        if (tid < tc) atomicAdd(&g_flag[sMeta[tid]], 1);
    }
}

// ---------------- launch -------------------------------------------------------
extern "C" void kernel_launch(void* const* d_in, const int* in_sizes, int n_in,
                              void* d_out, int out_size) {
    const int*   node_types      = (const int*)  d_in[0];
    const int*   node_vals       = (const int*)  d_in[1];
    const int*   last_parent     = (const int*)  d_in[3];
    const int*   child_positions = (const int*)  d_in[4];
    const float* type_emb        = (const float*)d_in[5];
    const float* pos_table       = (const float*)d_in[6];
    const float* token_emb       = (const float*)d_in[7];
    const float* w_ih            = (const float*)d_in[8];
    const float* w_hh            = (const float*)d_in[9];
    const float* b_ih            = (const float*)d_in[10];
    const float* b_hh            = (const float*)d_in[11];
    float* out = (float*)d_out;

    cudaFuncSetAttribute(gi_mma_kernel, cudaFuncAttributeMaxDynamicSharedMemorySize, GI_SMEM);

    prep_sched_kernel<<<BB, 256>>>(w_ih, w_hh, last_parent);
    embed_kernel<<<NB/4, 256>>>(node_types, node_vals, child_positions,
                                type_emb, pos_table, token_emb, out);
    gi_mma_kernel<<<NB/128, 512, GI_SMEM>>>(b_ih);
    seq_kernel<<<296, 256>>>(last_parent, b_hh, out);
}

// round 17
// speedup vs baseline: 1.2592x; 1.0945x over previous
#include <cuda_runtime.h>
#include <cuda_fp16.h>
#include <math.h>
#include <stdint.h>

// Problem constants
#define BB   64
#define NN   1024
#define DD   256
#define HH   256
#define G3   768            // 3*H
#define NB   (BB*NN)        // 65536 rows
#define TG   32             // rows per unit in seq kernel
#define PITCH 264           // fp16 pitch for A smem tiles (132 u32; LDSM conflict-free)

// ---------------- scratch (device globals) ------------------------------------
__device__ __align__(16) __half g_gi_h[NB*G3];  // input gates fp16 (96 MB)
__device__ __align__(16) __half g_h[NB*HH];     // hidden states fp16 (32 MB)
__device__ __align__(16) __half g_x_h[NB*DD];   // fp16 activations
// hi-only frag-packed weights: [n][ks][tq] -> uint2 {hi0, hi1}
__device__ __align__(16) uint2 g_wih_h2[G3*64];
__device__ __align__(16) uint2 g_whh_h2[G3*64];
__device__ int   g_rptr   [NN+1];
__device__ int   g_sched  [NB];
__device__ int   g_bmax   [BB];
__device__ int   g_maxd;
__device__ int   g_flag   [NB];      // per-node completion counter (4 quarters)
__device__ int   g_uptr   [NN+2];    // per-level unit prefix
__device__ int   g_stot   [NN];      // level totals (atomic-accumulated)
__device__ int   g_cursor [NN];      // per-level slot cursor
__device__ int   g_unit_total;
__device__ unsigned g_unit_ctr;
__device__ unsigned g_bar_count = 0;
__device__ unsigned g_bar_gen   = 0;
__device__ unsigned g_leaf_count[8];

// ---------------- helpers ------------------------------------------------------
__device__ __forceinline__ void mma16816(float* c,
        uint32_t a0, uint32_t a1, uint32_t a2, uint32_t a3,
        uint32_t b0, uint32_t b1) {
    asm("mma.sync.aligned.m16n8k16.row.col.f32.f16.f16.f32 "
        "{%0,%1,%2,%3}, {%4,%5,%6,%7}, {%8,%9}, {%0,%1,%2,%3};"
        : "+f"(c[0]), "+f"(c[1]), "+f"(c[2]), "+f"(c[3])
        : "r"(a0), "r"(a1), "r"(a2), "r"(a3), "r"(b0), "r"(b1));
}
__device__ __forceinline__ void ldsm4(uint32_t addr, uint32_t* r) {
    asm volatile("ldmatrix.sync.aligned.m8n8.x4.shared.b16 {%0,%1,%2,%3}, [%4];"
        : "=r"(r[0]), "=r"(r[1]), "=r"(r[2]), "=r"(r[3]) : "r"(addr));
}
__device__ __forceinline__ uint32_t smem_u32(const void* p) {
    uint32_t a;
    asm("{ .reg .u64 t; cvta.to.shared.u64 t, %1; cvt.u32.u64 %0, t; }" : "=r"(a) : "l"(p));
    return a;
}
__device__ __forceinline__ uint32_t pack_h2(float x, float y) {
    __half2 h = __floats2half2_rn(x, y);
    return *reinterpret_cast<uint32_t*>(&h);
}
__device__ __forceinline__ float2 unpack_h2(uint32_t v) {
    __half2 h = *reinterpret_cast<__half2*>(&v);
    return __half22float2(h);
}
__device__ __forceinline__ float sigm(float x) { return 1.0f / (1.0f + expf(-x)); }

// Hierarchical grid barrier (used only by prep_sched, 64 CTAs).
__device__ __forceinline__ void grid_barrier() {
    __threadfence();
    __syncthreads();
    if (threadIdx.x == 0) {
        unsigned gen = *(volatile unsigned*)&g_bar_gen;
        int leaf = blockIdx.x & 7;
        unsigned gsz = (gridDim.x >> 3) + ((blockIdx.x & 7) < (gridDim.x & 7) ? 1u : 0u);
        if (atomicAdd(&g_leaf_count[leaf], 1u) == gsz - 1u) {
            g_leaf_count[leaf] = 0u;
            __threadfence();
            if (atomicAdd(&g_bar_count, 1u) == 7u) {
                g_bar_count = 0u;
                __threadfence();
                *(volatile unsigned*)&g_bar_gen = gen + 1u;
            }
        }
        while (*(volatile unsigned*)&g_bar_gen == gen) { __nanosleep(64); }
        __threadfence();
    }
    __syncthreads();
}

// ---------------- fused prep + scheduler (64 CTAs x 256, parallel phase 1) -----
__global__ void __launch_bounds__(256) prep_sched_kernel(
        const float* __restrict__ wih, const float* __restrict__ whh,
        const int* __restrict__ lpi) {
    __shared__ int            jb[NN];
    __shared__ unsigned short db[NN];
    __shared__ int            scnt[NN];
    __shared__ int            scur[NN];
    __shared__ int            ssum[256];
    __shared__ int            smax;
    int b = blockIdx.x, tid = threadIdx.x;

    for (int e = b * 256 + tid; e < G3*64; e += 64*256) {
        int n  = e >> 6;
        int r  = e & 63;
        int ks = r >> 2, tq = r & 3;
        int k0 = 2*(ks*8 + tq);
        {
            uint2 v;
            v.x = pack_h2(wih[n*256 + k0],     wih[n*256 + k0 + 1]);
            v.y = pack_h2(wih[n*256 + k0 + 8], wih[n*256 + k0 + 9]);
            g_wih_h2[e] = v;
        }
        {
            uint2 v;
            v.x = pack_h2(whh[n*256 + k0],     whh[n*256 + k0 + 1]);
            v.y = pack_h2(whh[n*256 + k0 + 8], whh[n*256 + k0 + 9]);
            g_whh_h2[e] = v;
        }
    }
    for (int i = tid; i < NN; i += 256) g_flag[b*NN + i] = 0;
    if (tid < 16) g_stot[b*16 + tid] = 0;
    if (b == 0 && tid == 0) g_unit_ctr = 0u;

    if (tid == 0) smax = 0;
    for (int i = tid; i < NN; i += 256) {
        jb[i] = (i == 0) ? 0 : lpi[b*NN + i];
        db[i] = (i == 0) ? 0 : 1;
        scnt[i] = 0;
    }
    __syncthreads();
    #pragma unroll 1
    for (int s = 0; s < 10; s++) {
        int nd[4], nj[4];
        #pragma unroll
        for (int u = 0; u < 4; u++) {
            int i = tid + u * 256;
            int j = jb[i];
            nd[u] = db[i] + db[j];
            nj[u] = jb[j];
        }
        __syncthreads();
        #pragma unroll
        for (int u = 0; u < 4; u++) {
            int i = tid + u * 256;
            db[i] = (unsigned short)nd[u];
            jb[i] = nj[u];
        }
        __syncthreads();
    }
    int lm = 0;
    for (int i = tid; i < NN; i += 256) {
        atomicAdd(&scnt[db[i]], 1);
        lm = max(lm, (int)db[i]);
    }
    atomicMax(&smax, lm);
    __syncthreads();
    if (tid == 0) g_bmax[b] = smax;
    grid_barrier();

    for (int i = tid; i < NN; i += 256)
        if (scnt[i]) atomicAdd(&g_stot[i], scnt[i]);
    grid_barrier();

    if (b == 0) {
        int base = tid * 4;
        int v0 = g_stot[base], v1 = g_stot[base+1], v2 = g_stot[base+2], v3 = g_stot[base+3];
        ssum[tid] = v0 + v1 + v2 + v3;
        __syncthreads();
        if (tid == 0) {
            int acc = 0;
            for (int t = 0; t < 256; t++) { int x = ssum[t]; ssum[t] = acc; acc += x; }
        }
        __syncthreads();
        int acc = ssum[tid];
        int p0 = acc, p1 = acc + v0, p2 = p1 + v1, p3 = p2 + v2;
        g_rptr[base] = p0;   g_cursor[base] = p0;
        g_rptr[base+1] = p1; g_cursor[base+1] = p1;
        g_rptr[base+2] = p2; g_cursor[base+2] = p2;
        g_rptr[base+3] = p3; g_cursor[base+3] = p3;
        if (tid == 255) g_rptr[NN] = p3 + v3;
        __syncthreads();
        if (tid == 0) {
            int md = 0;
            for (int bb = 0; bb < BB; bb++) md = max(md, g_bmax[bb]);
            g_maxd = md;
            int uacc = 0;
            for (int r = 0; r <= md; r++) {
                g_uptr[r] = uacc;
                int cnt = g_rptr[r+1] - g_rptr[r];
                uacc += ((cnt + TG - 1) / TG) * 4;
            }
            g_uptr[md + 1] = uacc;
            g_unit_total = uacc;
        }
    }
    grid_barrier();

    for (int i = tid; i < NN; i += 256)
        scur[i] = scnt[i] ? atomicAdd(&g_cursor[i], scnt[i]) : 0;
    __syncthreads();

    for (int i = tid; i < NN; i += 256) {
        int d = db[i];
        int pos = atomicAdd(&scur[d], 1);
        g_sched[pos] = (b << 10) | i;
    }
}

// ---------------- embeddings + first half of output (float4, 4 nodes/block) ----
__global__ void __launch_bounds__(256) embed_kernel(
                             const int* __restrict__ node_types,
                             const int* __restrict__ node_vals,
                             const int* __restrict__ child_positions,
                             const float* __restrict__ type_emb,
                             const float* __restrict__ pos_table,
                             const float* __restrict__ token_emb,
                             float* __restrict__ out) {
    int tid = threadIdx.x;
    int id  = blockIdx.x * 4 + (tid >> 6);
    int j   = tid & 63;
    int b = id >> 10, n = id & 1023;
    int tt = node_types[id];
    int cp = child_positions[id];
    int v0 = node_vals[2*id];
    int v1 = node_vals[2*id + 1];
    float4 te = ((const float4*)type_emb)[tt*64 + j];
    float4 pe = ((const float4*)pos_table)[cp*64 + j];
    float4 t0 = ((const float4*)token_emb)[v0*64 + j];
    float4 t1 = ((const float4*)token_emb)[v1*64 + j];
    float4 x, o;
    x.x = te.x*4.0f + pe.x*0.25f;  x.y = te.y*4.0f + pe.y*0.25f;
    x.z = te.z*4.0f + pe.z*0.25f;  x.w = te.w*4.0f + pe.w*0.25f;
    o.x = x.x + (t0.x + t1.x)*2.0f;  o.y = x.y + (t0.y + t1.y)*2.0f;
    o.z = x.z + (t0.z + t1.z)*2.0f;  o.w = x.w + (t0.w + t1.w)*2.0f;
    ((float4*)(out + (long)(n*BB + b) * (DD+HH)))[j] = o;
    uint2 hx;
    hx.x = pack_h2(x.x, x.y);
    hx.y = pack_h2(x.z, x.w);
    ((uint2*)(g_x_h + (long)id * DD))[j] = hx;
}

// ---------------- GI GEMM: 512 threads, M=128/CTA, 3 N-chunks, single fp16 term
#define GI_SMEM (128 * PITCH * 2)   // fp16 A tile, bytes

__global__ void __launch_bounds__(512, 1) gi_mma_kernel(const float* __restrict__ bih) {
    extern __shared__ __half sA[];              // [128][PITCH]
    int tid = threadIdx.x;
    int wid = tid >> 5, lane = tid & 31;
    int gid = lane >> 2, tq = lane & 3;
    int wm = wid >> 3, wc = wid & 7;
    long row0 = (long)blockIdx.x * 128;

    {
        const uint32_t* src = (const uint32_t*)g_x_h + row0 * 128;
        uint32_t* dst = (uint32_t*)sA;
        for (int idx = tid; idx < 128 * 128; idx += 512) {
            int m = idx >> 7, j = idx & 127;
            dst[m * (PITCH/2) + j] = src[idx];
        }
    }
    __syncthreads();

    int l7 = lane & 7, q = lane >> 3;
    uint32_t aoff = (((q & 1) * 8 + l7) * (PITCH/2) + (q >> 1) * 4) * 4;
    uint32_t sAA = smem_u32(sA);
    uint32_t ad[4];
    #pragma unroll
    for (int mt = 0; mt < 4; mt++)
        ad[mt] = sAA + (wm * 64 + mt * 16) * (PITCH*2) + aoff;

    for (int c = 0; c < 3; c++) {
        float C[4][4][4];
        #pragma unroll
        for (int mt = 0; mt < 4; mt++)
            #pragma unroll
            for (int nt = 0; nt < 4; nt++)
                #pragma unroll
                for (int qq = 0; qq < 4; qq++) C[mt][nt][qq] = 0.0f;

        #pragma unroll 2
        for (int ks = 0; ks < 16; ks++) {
            uint32_t aF[4][4];
            #pragma unroll
            for (int mt = 0; mt < 4; mt++) ldsm4(ad[mt] + ks * 32, aF[mt]);
            uint2 bw[4];
            #pragma unroll
            for (int nt = 0; nt < 4; nt++) {
                int n = c * 256 + wc * 32 + nt * 8 + gid;
                bw[nt] = g_wih_h2[n * 64 + ks * 4 + tq];
            }
            #pragma unroll
            for (int nt = 0; nt < 4; nt++)
                #pragma unroll
                for (int mt = 0; mt < 4; mt++)
                    mma16816(C[mt][nt], aF[mt][0], aF[mt][1], aF[mt][2], aF[mt][3],
                             bw[nt].x, bw[nt].y);
        }
        #pragma unroll
        for (int mt = 0; mt < 4; mt++) {
            long r = row0 + wm * 64 + mt * 16 + gid;
            #pragma unroll
            for (int nt = 0; nt < 4; nt++) {
                int col = c * 256 + wc * 32 + nt * 8 + tq * 2;
                float2 bv = *(const float2*)(bih + col);
                *(uint32_t*)(g_gi_h + r * G3 + col) =
                    pack_h2(C[mt][nt][0] + bv.x, C[mt][nt][1] + bv.y);
                *(uint32_t*)(g_gi_h + (r + 8) * G3 + col) =
                    pack_h2(C[mt][nt][2] + bv.x, C[mt][nt][3] + bv.y);
            }
        }
    }
}

// ---------------- dataflow GRU kernel (persistent, 256 thr, 3 CTAs/SM) ---------
// Units in level order; unit = (row-group of TG=32, quarter of 64 output cols).
// Next-unit claim is software-pipelined: the atomic for unit k+1 issues at the
// top of unit k's work, hiding its latency. Deadlock-free: deps only point to
// strictly smaller unit indices; the holder of the smallest unstarted unit is
// always executing a smaller one.
__global__ void __launch_bounds__(256, 3) seq_kernel(const int* __restrict__ lpi,
                                                     const float* __restrict__ bhh,
                                                     float* __restrict__ out) {
    __shared__ __half sH[TG * PITCH];
    __shared__ int sMeta[TG];
    __shared__ int sPar[TG];
    __shared__ int sUptr[NN + 2];
    __shared__ int sU;
    int tid = threadIdx.x;
    int wid = tid >> 5, lane = tid & 31;
    int gid = lane >> 2, tq = lane & 3;
    int maxd = g_maxd;
    int total = g_unit_total;

    for (int i = tid; i <= maxd + 1; i += 256) sUptr[i] = g_uptr[i];

    int l7 = lane & 7, q = lane >> 3;
    uint32_t aoff = (((q & 1) * 8 + l7) * (PITCH/2) + (q >> 1) * 4) * 4;
    uint32_t sHA = smem_u32(sH);
    uint32_t ad[2];
    #pragma unroll
    for (int mt = 0; mt < 2; mt++)
        ad[mt] = sHA + (mt * 16) * (PITCH*2) + aoff;

    if (tid == 0) sU = (int)atomicAdd(&g_unit_ctr, 1u);
    __syncthreads();
    int u = sU;

    while (u < total) {
        // software-pipelined claim for the NEXT unit (latency overlaps work)
        if (tid == 0) sU = (int)atomicAdd(&g_unit_ctr, 1u);

        // binary search: largest r with sUptr[r] <= u
        int lo = 0, hi = maxd;
        while (lo < hi) {
            int mid = (lo + hi + 1) >> 1;
            if (sUptr[mid] <= u) lo = mid; else hi = mid - 1;
        }
        int r = lo;
        int start = g_rptr[r];
        int cnt   = g_rptr[r+1] - start;
        int local = u - sUptr[r];
        int gidx = local >> 2, quarter = local & 3;
        int t0 = start + gidx * TG;
        int tc = cnt - gidx * TG; if (tc > TG) tc = TG;
        if (tid < TG) {
            if (tid < tc) {
                int s = g_sched[t0 + tid];
                sMeta[tid] = s;
                int b = s >> 10, i = s & 1023;
                sPar[tid] = (i == 0) ? -1 : ((b << 10) | lpi[b*NN + i]);
            } else { sMeta[tid] = 0; sPar[tid] = -1; }
        }
        __syncthreads();

        int nbase = quarter * 64 + 8 * wid;
        int cp = nbase + tq * 2;               // this thread's output col

        // -------- prefetch g_gi gate words for this thread's 4 rows
        uint32_t preR[4], preZ[4], preN[4];
        #pragma unroll
        for (int mt = 0; mt < 2; mt++)
            #pragma unroll
            for (int rh = 0; rh < 2; rh++) {
                int lr = mt * 16 + gid + rh * 8;
                long row = (long)sMeta[lr];
                const __half* gp = g_gi_h + row * G3;
                preR[mt*2+rh] = *(const uint32_t*)(gp + cp);
                preZ[mt*2+rh] = *(const uint32_t*)(gp + 256 + cp);
                preN[mt*2+rh] = *(const uint32_t*)(gp + 512 + cp);
            }

        // -------- wait for parents (flag reaches 4 when fully written)
        if (tid < TG) {
            int pr = sPar[tid];
            if (pr >= 0) {
                const volatile int* fp = (const volatile int*)&g_flag[pr];
                while (*fp < 4) { __nanosleep(32); }
                __threadfence();
            }
        }
        __syncthreads();

        // gather parents (fp16 rows, straight uint4 copy) -> smem
        for (int idx = tid; idx < TG * 32; idx += 256) {
            int t = idx >> 5, k16 = idx & 31;
            int pr = sPar[t];
            uint4 v;
            if (pr < 0) { v.x = v.y = v.z = v.w = 0u; }
            else        { v = ((const uint4*)(g_h + (long)pr * HH))[k16]; }
            *(uint4*)((char*)sH + t * (PITCH*2) + k16 * 16) = v;
        }
        __syncthreads();

        float C[2][3][4];
        #pragma unroll
        for (int mt = 0; mt < 2; mt++)
            #pragma unroll
            for (int jj = 0; jj < 3; jj++)
                #pragma unroll
                for (int qq = 0; qq < 4; qq++) C[mt][jj][qq] = 0.0f;

        // double-buffered B frags across ks
        uint2 bwA[3], bwB[3];
        #pragma unroll
        for (int jj = 0; jj < 3; jj++)
            bwA[jj] = g_whh_h2[(jj*256 + nbase + gid) * 64 + tq];
        #pragma unroll 1
        for (int ks = 0; ks < 16; ks++) {
            uint2* cur = (ks & 1) ? bwB : bwA;
            uint2* nxt = (ks & 1) ? bwA : bwB;
            if (ks < 15) {
                #pragma unroll
                for (int jj = 0; jj < 3; jj++)
                    nxt[jj] = g_whh_h2[(jj*256 + nbase + gid) * 64 + (ks+1)*4 + tq];
            }
            uint32_t aF[2][4];
            #pragma unroll
            for (int mt = 0; mt < 2; mt++) ldsm4(ad[mt] + ks * 32, aF[mt]);
            #pragma unroll
            for (int jj = 0; jj < 3; jj++)
                #pragma unroll
                for (int mt = 0; mt < 2; mt++)
                    mma16816(C[mt][jj], aF[mt][0], aF[mt][1], aF[mt][2], aF[mt][3],
                             cur[jj].x, cur[jj].y);
        }

        // fused GRU epilogue using prefetched gates
        {
            float2 br = *(const float2*)(bhh + cp);
            float2 bz = *(const float2*)(bhh + 256 + cp);
            float2 bn = *(const float2*)(bhh + 512 + cp);
            #pragma unroll
            for (int mt = 0; mt < 2; mt++) {
                #pragma unroll
                for (int rh = 0; rh < 2; rh++) {
                    int lr = mt * 16 + gid + rh * 8;
                    if (lr >= tc) continue;
                    int s = sMeta[lr];
                    long row = (long)s;
                    int b = s >> 10, i = s & 1023;
                    float2 gr = unpack_h2(preR[mt*2+rh]);
                    float2 gz = unpack_h2(preZ[mt*2+rh]);
                    float2 gn = unpack_h2(preN[mt*2+rh]);
                    uint32_t hpw = *(const uint32_t*)((char*)sH + lr * (PITCH*2) + cp * 2);
                    float2 hp = unpack_h2(hpw);
                    float rg0 = sigm(gr.x + C[mt][0][rh*2]   + br.x);
                    float rg1 = sigm(gr.y + C[mt][0][rh*2+1] + br.y);
                    float zg0 = sigm(gz.x + C[mt][1][rh*2]   + bz.x);
                    float zg1 = sigm(gz.y + C[mt][1][rh*2+1] + bz.y);
                    float ng0 = tanhf(gn.x + (C[mt][2][rh*2]   + bn.x) * rg0);
                    float ng1 = tanhf(gn.y + (C[mt][2][rh*2+1] + bn.y) * rg1);
                    float h0 = (1.0f - zg0) * ng0 + zg0 * hp.x;
                    float h1 = (1.0f - zg1) * ng1 + zg1 * hp.y;
                    *(uint32_t*)(g_h + row * HH + cp) = pack_h2(h0, h1);
                    *(float2*)(out + ((long)(i*BB + b) * (DD+HH)) + DD + cp) = make_float2(h0, h1);
                }
            }
        }
        __threadfence();
        __syncthreads();
        if (tid < tc) atomicAdd(&g_flag[sMeta[tid]], 1);
        __syncthreads();
        u = sU;
    }
}

// ---------------- launch -------------------------------------------------------
extern "C" void kernel_launch(void* const* d_in, const int* in_sizes, int n_in,
                              void* d_out, int out_size) {
    const int*   node_types      = (const int*)  d_in[0];
    const int*   node_vals       = (const int*)  d_in[1];
    const int*   last_parent     = (const int*)  d_in[3];
    const int*   child_positions = (const int*)  d_in[4];
    const float* type_emb        = (const float*)d_in[5];
    const float* pos_table       = (const float*)d_in[6];
    const float* token_emb       = (const float*)d_in[7];
    const float* w_ih            = (const float*)d_in[8];
    const float* w_hh            = (const float*)d_in[9];
    const float* b_ih            = (const float*)d_in[10];
    const float* b_hh            = (const float*)d_in[11];
    float* out = (float*)d_out;

    cudaFuncSetAttribute(gi_mma_kernel, cudaFuncAttributeMaxDynamicSharedMemorySize, GI_SMEM);

    prep_sched_kernel<<<BB, 256>>>(w_ih, w_hh, last_parent);
    embed_kernel<<<NB/4, 256>>>(node_types, node_vals, child_positions,
                                type_emb, pos_table, token_emb, out);
    gi_mma_kernel<<<NB/128, 512, GI_SMEM>>>(b_ih);
    seq_kernel<<<444, 256>>>(last_parent, b_hh, out);
}